// round 13
// baseline (speedup 1.0000x reference)
#include <cuda_runtime.h>
#include <math.h>
#include <stdint.h>

#define Bq 4
#define Cc 32
#define Hh 128
#define Ww 128
#define HW (Hh*Ww)
#define BHW (Bq*HW)
#define MSIZE 512
#define HD 8

typedef unsigned long long ull;

__device__ __forceinline__ ull pk2(float lo, float hi) {
    ull r; asm("mov.b64 %0,{%1,%2};" : "=l"(r) : "f"(lo), "f"(hi)); return r;
}
__device__ __forceinline__ void upk2(float& lo, float& hi, ull v) {
    asm("mov.b64 {%0,%1},%2;" : "=f"(lo), "=f"(hi) : "l"(v));
}
__device__ __forceinline__ void fma2(ull& d, ull a, ull b, ull c) {
    asm("fma.rn.f32x2 %0,%1,%2,%3;" : "=l"(d) : "l"(a), "l"(b), "l"(c));
}
__device__ __forceinline__ float ex2f(float x) {
    float r; asm("ex2.approx.f32 %0,%1;" : "=f"(r) : "f"(x)); return r;
}
__device__ __forceinline__ uint32_t tf32c(float f) {
    uint32_t r; asm("cvt.rna.tf32.f32 %0,%1;" : "=r"(r) : "f"(f)); return r;
}
#define MMA168(d0,d1,d2,d3,a0,a1,a2,a3,b0,b1) \
  asm("mma.sync.aligned.m16n8k8.row.col.f32.tf32.tf32.f32 " \
      "{%0,%1,%2,%3}, {%4,%5,%6,%7}, {%8,%9}, {%0,%1,%2,%3};" \
      : "+f"(d0),"+f"(d1),"+f"(d2),"+f"(d3) \
      : "r"(a0),"r"(a1),"r"(a2),"r"(a3),"r"(b0),"r"(b1))

// scratch (no allocs allowed)
__device__ float g_x3[Bq*Cc*HW];
__device__ float g_om[27*BHW];     // offset-conv output, [j][p]
__device__ float g_yavg[Bq*Cc];
__device__ float g_ysp[Bq*Cc];
__device__ float g_ych[Bq*Cc];

// ---------------- kernel 1: per-(b,c) spatial mean ----------------
__global__ void k_avg(const float* __restrict__ x) {
    int bc = blockIdx.x;
    const float* p = x + bc * HW;
    float s = 0.f;
    for (int i = threadIdx.x; i < HW; i += 256) s += p[i];
    __shared__ float red[256];
    red[threadIdx.x] = s; __syncthreads();
    for (int st = 128; st > 0; st >>= 1) {
        if (threadIdx.x < st) red[threadIdx.x] += red[threadIdx.x + st];
        __syncthreads();
    }
    if (threadIdx.x == 0) g_yavg[bc] = red[0] * (1.0f / (float)HW);
}

// ---------------- kernel 2: tiny squeeze MLPs ----------------
__global__ void k_mlp(const float* __restrict__ fs_w1, const float* __restrict__ fs_w2,
                      const float* __restrict__ fc_w1, const float* __restrict__ fc_w2) {
    __shared__ float ys[Bq*Cc];
    int t = threadIdx.x;           // 128 threads, t = b*32+c
    ys[t] = g_yavg[t];
    __syncthreads();
    int b = t >> 5, c = t & 31;
    const float* yb = ys + b * 32;
    float hs0 = 0.f, hs1 = 0.f;
    #pragma unroll
    for (int j = 0; j < 32; j++) { hs0 += yb[j] * fs_w1[j]; hs1 += yb[j] * fs_w1[32 + j]; }
    hs0 = fmaxf(hs0, 0.f); hs1 = fmaxf(hs1, 0.f);
    float sp = hs0 * fs_w2[c*2 + 0] + hs1 * fs_w2[c*2 + 1];
    g_ysp[t] = 1.f / (1.f + __expf(-sp));
    float ch = 0.f;
    #pragma unroll
    for (int r = 0; r < 4; r++) {
        float a = 0.f;
        #pragma unroll
        for (int j = 0; j < 32; j++) a += yb[j] * fc_w1[r*32 + j];
        ch += fmaxf(a, 0.f) * fc_w2[c*4 + r];
    }
    g_ych[t] = 1.f / (1.f + __expf(-ch));
}

// ---------------- kernel 3a: offset conv (3x3, 32->27) ----------------
__global__ __launch_bounds__(128) void k_off(
    const float* __restrict__ x,
    const float* __restrict__ off_w, const float* __restrict__ off_b)
{
    __shared__ __align__(16) float wbuf[9*32*28];
    __shared__ float bbuf[28];
    int tid = threadIdx.x;
    for (int i = tid; i < 7776; i += 128) {
        int j = i / 288, r = i - j*288, c = r / 9, k = r - c*9;
        wbuf[(k*32 + c)*28 + j] = off_w[i];
    }
    for (int i = tid; i < 288; i += 128) wbuf[i*28 + 27] = 0.f;
    if (tid < 27) bbuf[tid] = off_b[tid];
    if (tid == 27) bbuf[27] = 0.f;
    __syncthreads();

    int x0i = tid;
    int b  = blockIdx.x >> 6;
    int y0 = (blockIdx.x & 63) * 2;
    const float* xb = x + ((long)b << 19);

    ull omA[14], omB[14];
    #pragma unroll
    for (int j = 0; j < 14; j++) { omA[j] = pk2(bbuf[2*j], bbuf[2*j+1]); omB[j] = omA[j]; }

    for (int ky = 0; ky < 3; ky++) {
        int yyA = y0 + ky - 1;
        int yyB = yyA + 1;
        bool okA = (yyA >= 0) & (yyA <= 127);
        bool okB = (yyB >= 0) & (yyB <= 127);
        for (int kx = 0; kx < 3; kx++) {
            int xx = x0i + kx - 1;
            bool okx = (xx >= 0) & (xx <= 127);
            bool vA = okA & okx, vB = okB & okx;
            if (!vA && !vB) continue;
            int kidx = ky*3 + kx;
            const float* xpA = xb + yyA*128 + xx;
            const float* xpB = xpA + 128;
            const float* wb0 = wbuf + kidx*32*28;
            #pragma unroll 4
            for (int c = 0; c < 32; c++) {
                float a = vA ? xpA[c << 14] : 0.f;
                float bb = vB ? xpB[c << 14] : 0.f;
                ull a2 = pk2(a, a), b2 = pk2(bb, bb);
                const ulonglong2* wp = (const ulonglong2*)(wb0 + c*28);
                #pragma unroll
                for (int i = 0; i < 7; i++) {
                    ulonglong2 u = wp[i];
                    fma2(omA[2*i],   a2, u.x, omA[2*i]);
                    fma2(omA[2*i+1], a2, u.y, omA[2*i+1]);
                    fma2(omB[2*i],   b2, u.x, omB[2*i]);
                    fma2(omB[2*i+1], b2, u.y, omB[2*i+1]);
                }
            }
        }
    }
    int pA = (b << 14) + y0*128 + x0i;
    int pB = pA + 128;
    #pragma unroll
    for (int j = 0; j < 14; j++) {
        float a0, a1; upk2(a0, a1, omA[j]);
        float b0, b1; upk2(b0, b1, omB[j]);
        g_om[(2*j)*BHW + pA] = a0;
        g_om[(2*j)*BHW + pB] = b0;
        if (2*j + 1 < 27) {
            g_om[(2*j+1)*BHW + pA] = a1;
            g_om[(2*j+1)*BHW + pB] = b1;
        }
    }
}

// ---------------- kernel 3b: deformable gather + 3x3 conv ----------------
// R4 structure; launch_bounds(256,3) to lift occupancy 16->24 warps/SM.
__global__ __launch_bounds__(256, 3) void k_dcn2(
    const float* __restrict__ x,
    const float* __restrict__ dcn_w, const float* __restrict__ dcn_b)
{
    __shared__ __align__(16) float wbuf[9216];
    __shared__ float bbuf[32];
    int tid = threadIdx.x;
    for (int i = tid; i < 9216; i += 256) {
        int o = i / 288, r = i - o*288, c = r / 9, k = r - c*9;
        wbuf[(k*32 + c)*32 + o] = dcn_w[i];
    }
    if (tid < 32) bbuf[tid] = dcn_b[tid];
    __syncthreads();

    int p = blockIdx.x * 256 + tid;
    int b = p >> 14;
    int rem = p & 16383;
    int y = rem >> 7, x0i = rem & 127;
    const float* xb = x + ((long)b << 19);

    ull acc2[16];
    #pragma unroll
    for (int i = 0; i < 16; i++) acc2[i] = pk2(bbuf[2*i], bbuf[2*i+1]);

    for (int k = 0; k < 9; k++) {
        float ofy = g_om[(2*k)*BHW + p];
        float ofx = g_om[(2*k+1)*BHW + p];
        float msk = 1.f / (1.f + __expf(-g_om[(18+k)*BHW + p]));
        float py = (float)(y   + k/3 - 1) + ofy;
        float px = (float)(x0i + k%3 - 1) + ofx;
        py = fminf(fmaxf(py, -4.0f), 131.0f);
        px = fminf(fmaxf(px, -4.0f), 131.0f);
        float fy = floorf(py), fx = floorf(px);
        float wy = py - fy, wx = px - fx;
        int iy0 = (int)fy, ix0 = (int)fx, iy1 = iy0 + 1, ix1 = ix0 + 1;
        float vy0 = (iy0 >= 0 && iy0 <= 127) ? 1.f : 0.f;
        float vy1 = (iy1 >= 0 && iy1 <= 127) ? 1.f : 0.f;
        float vx0 = (ix0 >= 0 && ix0 <= 127) ? 1.f : 0.f;
        float vx1 = (ix1 >= 0 && ix1 <= 127) ? 1.f : 0.f;
        float w00 = (1.f - wy) * (1.f - wx) * vy0 * vx0 * msk;
        float w01 = (1.f - wy) * wx         * vy0 * vx1 * msk;
        float w10 = wy         * (1.f - wx) * vy1 * vx0 * msk;
        float w11 = wy         * wx         * vy1 * vx1 * msk;
        int cy0 = min(max(iy0, 0), 127), cy1 = min(max(iy1, 0), 127);
        int cx0 = min(max(ix0, 0), 127), cx1 = min(max(ix1, 0), 127);
        int a00 = cy0*128 + cx0, a01 = cy0*128 + cx1;
        int a10 = cy1*128 + cx0, a11 = cy1*128 + cx1;
        for (int c = 0; c < 32; c++) {
            const float* xp = xb + (c << 14);
            float val = w00 * xp[a00] + w01 * xp[a01] + w10 * xp[a10] + w11 * xp[a11];
            ull v2 = pk2(val, val);
            const ulonglong2* wp = (const ulonglong2*)(wbuf + (k*32 + c)*32);
            #pragma unroll
            for (int i = 0; i < 8; i++) {
                ulonglong2 u = wp[i];
                fma2(acc2[2*i],   v2, u.x, acc2[2*i]);
                fma2(acc2[2*i+1], v2, u.y, acc2[2*i+1]);
            }
        }
    }
    float* x3p = g_x3 + ((long)b << 19) + y*128 + x0i;
    #pragma unroll
    for (int i = 0; i < 16; i++) {
        float a, bfl; upk2(a, bfl, acc2[i]);
        x3p[(2*i) << 14]   = a;
        x3p[(2*i+1) << 14] = bfl;
    }
}

// ---------------- kernel 4: switch-conv via tf32 tensor cores ----------------
// Block = 128 px (one row chunk), 8 warps x 16 px. GEMM [128x64]x[64x32] -> h1,
// epilogue relu + W2 dot in-fragment + quad reduce, coalesced xo write.
__global__ __launch_bounds__(256) void k_conv(
    const float* __restrict__ x,
    const float* __restrict__ sw_w1, const float* __restrict__ sw_b1,
    const float* __restrict__ sw_w2, const float* __restrict__ sw_b2,
    float* __restrict__ out)
{
    __shared__ __align__(16) float xs[64][136];   // 34.8KB, pad 136 -> banks 8q+r
    __shared__ __align__(16) uint2 w1f[8][4][32]; // 8KB: B frags
    __shared__ float w2s[64], b1s[32], b2s[2];
    __shared__ float ysps[32], ychs[32];
    __shared__ float sbuf[2][128];

    int tid = threadIdx.x;
    int p0 = blockIdx.x * 128;
    int b = p0 >> 14, sp0 = p0 & 16383;
    long gbase = ((long)b << 19) + sp0;

    for (int i = tid; i < 8192; i += 256) {
        int c = i >> 7, px = i & 127;
        xs[c][px] = (c < 32) ? x[gbase + ((long)c << 14) + px]
                             : g_x3[gbase + ((long)(c - 32) << 14) + px];
    }
    // B frag: b0 = W1col[k][o], b1 = W1col[k+4][o]; W1col[c][o] = sw_w1[o*64+c]
    for (int i = tid; i < 1024; i += 256) {
        int t = i >> 7, rem2 = i & 127, n = rem2 >> 5, lane = rem2 & 31;
        int k = t*8 + (lane & 3), o = n*8 + (lane >> 2);
        w1f[t][n][lane] = make_uint2(tf32c(sw_w1[o*64 + k]), tf32c(sw_w1[o*64 + k + 4]));
    }
    if (tid < 64) w2s[tid] = sw_w2[tid];
    if (tid < 32) { b1s[tid] = sw_b1[tid]; ysps[tid] = g_ysp[b*32 + tid]; ychs[tid] = g_ych[b*32 + tid]; }
    if (tid < 2)  b2s[tid] = sw_b2[tid];
    __syncthreads();

    int w = tid >> 5, lane = tid & 31;
    int r = lane >> 2, q = lane & 3;
    int m0 = w * 16;

    float d[4][4] = {{0.f}};
    #pragma unroll
    for (int t = 0; t < 8; t++) {
        uint32_t a0 = tf32c(xs[t*8 + q    ][m0 + r]);
        uint32_t a1 = tf32c(xs[t*8 + q    ][m0 + r + 8]);
        uint32_t a2 = tf32c(xs[t*8 + q + 4][m0 + r]);
        uint32_t a3 = tf32c(xs[t*8 + q + 4][m0 + r + 8]);
        #pragma unroll
        for (int n = 0; n < 4; n++) {
            uint2 bf = w1f[t][n][lane];
            MMA168(d[n][0], d[n][1], d[n][2], d[n][3], a0, a1, a2, a3, bf.x, bf.y);
        }
    }
    float sA0 = 0.f, sA1 = 0.f, sB0 = 0.f, sB1 = 0.f;
    #pragma unroll
    for (int n = 0; n < 4; n++) {
        int o0 = n*8 + 2*q, o1 = o0 + 1;
        float h00 = fmaxf(d[n][0] + b1s[o0], 0.f);
        float h01 = fmaxf(d[n][1] + b1s[o1], 0.f);
        float h10 = fmaxf(d[n][2] + b1s[o0], 0.f);
        float h11 = fmaxf(d[n][3] + b1s[o1], 0.f);
        sA0 += h00*w2s[o0]      + h01*w2s[o1];
        sA1 += h00*w2s[32 + o0] + h01*w2s[32 + o1];
        sB0 += h10*w2s[o0]      + h11*w2s[o1];
        sB1 += h10*w2s[32 + o0] + h11*w2s[32 + o1];
    }
    sA0 += __shfl_xor_sync(0xffffffffu, sA0, 1); sA0 += __shfl_xor_sync(0xffffffffu, sA0, 2);
    sA1 += __shfl_xor_sync(0xffffffffu, sA1, 1); sA1 += __shfl_xor_sync(0xffffffffu, sA1, 2);
    sB0 += __shfl_xor_sync(0xffffffffu, sB0, 1); sB0 += __shfl_xor_sync(0xffffffffu, sB0, 2);
    sB1 += __shfl_xor_sync(0xffffffffu, sB1, 1); sB1 += __shfl_xor_sync(0xffffffffu, sB1, 2);
    if (q == 0) {
        sbuf[0][m0 + r]     = 1.f / (1.f + __expf(-(sA0 + b2s[0])));
        sbuf[1][m0 + r]     = 1.f / (1.f + __expf(-(sA1 + b2s[1])));
        sbuf[0][m0 + r + 8] = 1.f / (1.f + __expf(-(sB0 + b2s[0])));
        sbuf[1][m0 + r + 8] = 1.f / (1.f + __expf(-(sB1 + b2s[1])));
    }
    __syncthreads();
    for (int i = tid; i < 4096; i += 256) {
        int c = i >> 7, px = i & 127;
        out[gbase + ((long)c << 14) + px] = xs[c][px] + ysps[c]*sbuf[0][px] + ychs[c]*sbuf[1][px];
    }
}

// ---------------- kernel 5: memory attention via tf32 tensor cores (R12) ----------------
__global__ __launch_bounds__(256) void k_attn(
    const float* __restrict__ mem, float* __restrict__ out)
{
    __shared__ __align__(16) uint2 b1buf[64*32];
    __shared__ __align__(16) uint2 b2buf[64*32];
    int tid = threadIdx.x;
    int hd = blockIdx.y;
    const float RSL = 0.35355339059327373f * 1.4426950408889634f;
    const int SIG[8] = {0,4,1,5,2,6,3,7};

    const float* mh = mem + hd*MSIZE*HD;
    for (int j = tid; j < 2048; j += 256) {
        int t = j >> 5, i = j & 31;
        int c = i >> 2, r = i & 3;
        int s1 = 8*t + SIG[c];
        b1buf[j] = make_uint2(tf32c(mh[s1*8 + r] * RSL), tf32c(mh[s1*8 + r + 4] * RSL));
        b2buf[j] = make_uint2(tf32c(mh[(8*t + r)*8 + c]), tf32c(mh[(8*t + r + 4)*8 + c]));
    }
    __syncthreads();

    int w = tid >> 5, lane = tid & 31;
    int p0 = blockIdx.x * 128 + w * 16;
    int b = p0 >> 14, sp0 = p0 & 16383;
    int r = lane >> 2, q = lane & 3;
    long base = ((long)b << 19) + ((long)(hd*8) << 14);
    int spA = sp0 + r, spB = sp0 + r + 8;

    uint32_t a0 = tf32c(out[base + ((long)q << 14) + spA]);
    uint32_t a1 = tf32c(out[base + ((long)q << 14) + spB]);
    uint32_t a2 = tf32c(out[base + ((long)(q+4) << 14) + spA]);
    uint32_t a3 = tf32c(out[base + ((long)(q+4) << 14) + spB]);

    float cE0=0.f,cE1=0.f,cE2=0.f,cE3=0.f;
    float cO0=0.f,cO1=0.f,cO2=0.f,cO3=0.f;
    float ls0 = 0.f, ls1 = 0.f;

    #pragma unroll 4
    for (int t = 0; t < 64; t += 2) {
        {
            uint2 b1 = b1buf[t*32 + lane];
            float s0=0.f,s1v=0.f,s2=0.f,s3=0.f;
            MMA168(s0,s1v,s2,s3, a0,a1,a2,a3, b1.x,b1.y);
            float e0 = ex2f(s0), e1 = ex2f(s1v), e2 = ex2f(s2), e3 = ex2f(s3);
            ls0 += e0 + e1; ls1 += e2 + e3;
            uint32_t pa0 = tf32c(e0), pa1 = tf32c(e2), pa2 = tf32c(e1), pa3 = tf32c(e3);
            uint2 b2 = b2buf[t*32 + lane];
            MMA168(cE0,cE1,cE2,cE3, pa0,pa1,pa2,pa3, b2.x,b2.y);
        }
        {
            uint2 b1 = b1buf[(t+1)*32 + lane];
            float s0=0.f,s1v=0.f,s2=0.f,s3=0.f;
            MMA168(s0,s1v,s2,s3, a0,a1,a2,a3, b1.x,b1.y);
            float e0 = ex2f(s0), e1 = ex2f(s1v), e2 = ex2f(s2), e3 = ex2f(s3);
            ls0 += e0 + e1; ls1 += e2 + e3;
            uint32_t pa0 = tf32c(e0), pa1 = tf32c(e2), pa2 = tf32c(e1), pa3 = tf32c(e3);
            uint2 b2 = b2buf[(t+1)*32 + lane];
            MMA168(cO0,cO1,cO2,cO3, pa0,pa1,pa2,pa3, b2.x,b2.y);
        }
    }
    float c0 = cE0 + cO0, c1 = cE1 + cO1, c2 = cE2 + cO2, c3 = cE3 + cO3;

    ls0 += __shfl_xor_sync(0xffffffffu, ls0, 1);
    ls0 += __shfl_xor_sync(0xffffffffu, ls0, 2);
    ls1 += __shfl_xor_sync(0xffffffffu, ls1, 1);
    ls1 += __shfl_xor_sync(0xffffffffu, ls1, 2);
    float inv0 = 1.f / ls0, inv1 = 1.f / ls1;

    long oA0 = base + ((long)(2*q)   << 14) + spA;
    long oA1 = base + ((long)(2*q+1) << 14) + spA;
    long oB0 = base + ((long)(2*q)   << 14) + spB;
    long oB1 = base + ((long)(2*q+1) << 14) + spB;
    out[oA0] += c0 * inv0;
    out[oA1] += c1 * inv0;
    out[oB0] += c2 * inv1;
    out[oB1] += c3 * inv1;
}

extern "C" void kernel_launch(void* const* d_in, const int* in_sizes, int n_in,
                              void* d_out, int out_size) {
    const float* x     = (const float*)d_in[0];
    const float* fs_w1 = (const float*)d_in[1];
    const float* fs_w2 = (const float*)d_in[2];
    const float* fc_w1 = (const float*)d_in[3];
    const float* fc_w2 = (const float*)d_in[4];
    const float* sw_w1 = (const float*)d_in[5];
    const float* sw_b1 = (const float*)d_in[6];
    const float* sw_w2 = (const float*)d_in[7];
    const float* sw_b2 = (const float*)d_in[8];
    const float* off_w = (const float*)d_in[9];
    const float* off_b = (const float*)d_in[10];
    const float* dcn_w = (const float*)d_in[11];
    const float* dcn_b = (const float*)d_in[12];
    const float* mem   = (const float*)d_in[13];
    float* out = (float*)d_out;

    k_avg<<<Bq*Cc, 256>>>(x);
    k_mlp<<<1, 128>>>(fs_w1, fs_w2, fc_w1, fc_w2);
    k_off<<<256, 128>>>(x, off_w, off_b);
    k_dcn2<<<BHW/256, 256>>>(x, dcn_w, dcn_b);
    k_conv<<<BHW/128, 256>>>(x, sw_w1, sw_b1, sw_w2, sw_b2, out);
    dim3 ag(BHW/128, 4);
    k_attn<<<ag, 256>>>(mem, out);
}

// round 14
// speedup vs baseline: 1.0375x; 1.0375x over previous
#include <cuda_runtime.h>
#include <math.h>
#include <stdint.h>

#define Bq 4
#define Cc 32
#define Hh 128
#define Ww 128
#define HW (Hh*Ww)
#define BHW (Bq*HW)
#define MSIZE 512
#define HD 8

typedef unsigned long long ull;

__device__ __forceinline__ ull pk2(float lo, float hi) {
    ull r; asm("mov.b64 %0,{%1,%2};" : "=l"(r) : "f"(lo), "f"(hi)); return r;
}
__device__ __forceinline__ void upk2(float& lo, float& hi, ull v) {
    asm("mov.b64 {%0,%1},%2;" : "=f"(lo), "=f"(hi) : "l"(v));
}
__device__ __forceinline__ void fma2(ull& d, ull a, ull b, ull c) {
    asm("fma.rn.f32x2 %0,%1,%2,%3;" : "=l"(d) : "l"(a), "l"(b), "l"(c));
}
__device__ __forceinline__ float ex2f(float x) {
    float r; asm("ex2.approx.f32 %0,%1;" : "=f"(r) : "f"(x)); return r;
}
__device__ __forceinline__ uint32_t tf32c(float f) {
    uint32_t r; asm("cvt.rna.tf32.f32 %0,%1;" : "=r"(r) : "f"(f)); return r;
}
#define MMA168(d0,d1,d2,d3,a0,a1,a2,a3,b0,b1) \
  asm("mma.sync.aligned.m16n8k8.row.col.f32.tf32.tf32.f32 " \
      "{%0,%1,%2,%3}, {%4,%5,%6,%7}, {%8,%9}, {%0,%1,%2,%3};" \
      : "+f"(d0),"+f"(d1),"+f"(d2),"+f"(d3) \
      : "r"(a0),"r"(a1),"r"(a2),"r"(a3),"r"(b0),"r"(b1))

// scratch (no allocs allowed)
__device__ float g_x3[Bq*Cc*HW];
__device__ float g_om[27*BHW];     // offset-conv output, [j][p]
__device__ float g_yavg[Bq*Cc];
__device__ float g_ysp[Bq*Cc];
__device__ float g_ych[Bq*Cc];

// ---------------- kernel 1: per-(b,c) spatial mean ----------------
__global__ void k_avg(const float* __restrict__ x) {
    int bc = blockIdx.x;
    const float* p = x + bc * HW;
    float s = 0.f;
    for (int i = threadIdx.x; i < HW; i += 256) s += p[i];
    __shared__ float red[256];
    red[threadIdx.x] = s; __syncthreads();
    for (int st = 128; st > 0; st >>= 1) {
        if (threadIdx.x < st) red[threadIdx.x] += red[threadIdx.x + st];
        __syncthreads();
    }
    if (threadIdx.x == 0) g_yavg[bc] = red[0] * (1.0f / (float)HW);
}

// ---------------- kernel 2: tiny squeeze MLPs ----------------
__global__ void k_mlp(const float* __restrict__ fs_w1, const float* __restrict__ fs_w2,
                      const float* __restrict__ fc_w1, const float* __restrict__ fc_w2) {
    __shared__ float ys[Bq*Cc];
    int t = threadIdx.x;           // 128 threads, t = b*32+c
    ys[t] = g_yavg[t];
    __syncthreads();
    int b = t >> 5, c = t & 31;
    const float* yb = ys + b * 32;
    float hs0 = 0.f, hs1 = 0.f;
    #pragma unroll
    for (int j = 0; j < 32; j++) { hs0 += yb[j] * fs_w1[j]; hs1 += yb[j] * fs_w1[32 + j]; }
    hs0 = fmaxf(hs0, 0.f); hs1 = fmaxf(hs1, 0.f);
    float sp = hs0 * fs_w2[c*2 + 0] + hs1 * fs_w2[c*2 + 1];
    g_ysp[t] = 1.f / (1.f + __expf(-sp));
    float ch = 0.f;
    #pragma unroll
    for (int r = 0; r < 4; r++) {
        float a = 0.f;
        #pragma unroll
        for (int j = 0; j < 32; j++) a += yb[j] * fc_w1[r*32 + j];
        ch += fmaxf(a, 0.f) * fc_w2[c*4 + r];
    }
    g_ych[t] = 1.f / (1.f + __expf(-ch));
}

// ---------------- kernel 3a: offset conv (3x3, 32->27) ----------------
__global__ __launch_bounds__(128) void k_off(
    const float* __restrict__ x,
    const float* __restrict__ off_w, const float* __restrict__ off_b)
{
    __shared__ __align__(16) float wbuf[9*32*28];
    __shared__ float bbuf[28];
    int tid = threadIdx.x;
    for (int i = tid; i < 7776; i += 128) {
        int j = i / 288, r = i - j*288, c = r / 9, k = r - c*9;
        wbuf[(k*32 + c)*28 + j] = off_w[i];
    }
    for (int i = tid; i < 288; i += 128) wbuf[i*28 + 27] = 0.f;
    if (tid < 27) bbuf[tid] = off_b[tid];
    if (tid == 27) bbuf[27] = 0.f;
    __syncthreads();

    int x0i = tid;
    int b  = blockIdx.x >> 6;
    int y0 = (blockIdx.x & 63) * 2;
    const float* xb = x + ((long)b << 19);

    ull omA[14], omB[14];
    #pragma unroll
    for (int j = 0; j < 14; j++) { omA[j] = pk2(bbuf[2*j], bbuf[2*j+1]); omB[j] = omA[j]; }

    for (int ky = 0; ky < 3; ky++) {
        int yyA = y0 + ky - 1;
        int yyB = yyA + 1;
        bool okA = (yyA >= 0) & (yyA <= 127);
        bool okB = (yyB >= 0) & (yyB <= 127);
        for (int kx = 0; kx < 3; kx++) {
            int xx = x0i + kx - 1;
            bool okx = (xx >= 0) & (xx <= 127);
            bool vA = okA & okx, vB = okB & okx;
            if (!vA && !vB) continue;
            int kidx = ky*3 + kx;
            const float* xpA = xb + yyA*128 + xx;
            const float* xpB = xpA + 128;
            const float* wb0 = wbuf + kidx*32*28;
            #pragma unroll 4
            for (int c = 0; c < 32; c++) {
                float a = vA ? xpA[c << 14] : 0.f;
                float bb = vB ? xpB[c << 14] : 0.f;
                ull a2 = pk2(a, a), b2 = pk2(bb, bb);
                const ulonglong2* wp = (const ulonglong2*)(wb0 + c*28);
                #pragma unroll
                for (int i = 0; i < 7; i++) {
                    ulonglong2 u = wp[i];
                    fma2(omA[2*i],   a2, u.x, omA[2*i]);
                    fma2(omA[2*i+1], a2, u.y, omA[2*i+1]);
                    fma2(omB[2*i],   b2, u.x, omB[2*i]);
                    fma2(omB[2*i+1], b2, u.y, omB[2*i+1]);
                }
            }
        }
    }
    int pA = (b << 14) + y0*128 + x0i;
    int pB = pA + 128;
    #pragma unroll
    for (int j = 0; j < 14; j++) {
        float a0, a1; upk2(a0, a1, omA[j]);
        float b0, b1; upk2(b0, b1, omB[j]);
        g_om[(2*j)*BHW + pA] = a0;
        g_om[(2*j)*BHW + pB] = b0;
        if (2*j + 1 < 27) {
            g_om[(2*j+1)*BHW + pA] = a1;
            g_om[(2*j+1)*BHW + pB] = b1;
        }
    }
}

// ---------------- kernel 3b: deformable gather + 3x3 conv (exact R4 best: 74.2us) ----------------
__global__ __launch_bounds__(256) void k_dcn2(
    const float* __restrict__ x,
    const float* __restrict__ dcn_w, const float* __restrict__ dcn_b)
{
    __shared__ __align__(16) float wbuf[9216];
    __shared__ float bbuf[32];
    int tid = threadIdx.x;
    for (int i = tid; i < 9216; i += 256) {
        int o = i / 288, r = i - o*288, c = r / 9, k = r - c*9;
        wbuf[(k*32 + c)*32 + o] = dcn_w[i];
    }
    if (tid < 32) bbuf[tid] = dcn_b[tid];
    __syncthreads();

    int p = blockIdx.x * 256 + tid;
    int b = p >> 14;
    int rem = p & 16383;
    int y = rem >> 7, x0i = rem & 127;
    const float* xb = x + ((long)b << 19);

    ull acc2[16];
    #pragma unroll
    for (int i = 0; i < 16; i++) acc2[i] = pk2(bbuf[2*i], bbuf[2*i+1]);

    for (int k = 0; k < 9; k++) {
        float ofy = g_om[(2*k)*BHW + p];
        float ofx = g_om[(2*k+1)*BHW + p];
        float msk = 1.f / (1.f + __expf(-g_om[(18+k)*BHW + p]));
        float py = (float)(y   + k/3 - 1) + ofy;
        float px = (float)(x0i + k%3 - 1) + ofx;
        py = fminf(fmaxf(py, -4.0f), 131.0f);
        px = fminf(fmaxf(px, -4.0f), 131.0f);
        float fy = floorf(py), fx = floorf(px);
        float wy = py - fy, wx = px - fx;
        int iy0 = (int)fy, ix0 = (int)fx, iy1 = iy0 + 1, ix1 = ix0 + 1;
        float vy0 = (iy0 >= 0 && iy0 <= 127) ? 1.f : 0.f;
        float vy1 = (iy1 >= 0 && iy1 <= 127) ? 1.f : 0.f;
        float vx0 = (ix0 >= 0 && ix0 <= 127) ? 1.f : 0.f;
        float vx1 = (ix1 >= 0 && ix1 <= 127) ? 1.f : 0.f;
        float w00 = (1.f - wy) * (1.f - wx) * vy0 * vx0 * msk;
        float w01 = (1.f - wy) * wx         * vy0 * vx1 * msk;
        float w10 = wy         * (1.f - wx) * vy1 * vx0 * msk;
        float w11 = wy         * wx         * vy1 * vx1 * msk;
        int cy0 = min(max(iy0, 0), 127), cy1 = min(max(iy1, 0), 127);
        int cx0 = min(max(ix0, 0), 127), cx1 = min(max(ix1, 0), 127);
        int a00 = cy0*128 + cx0, a01 = cy0*128 + cx1;
        int a10 = cy1*128 + cx0, a11 = cy1*128 + cx1;
        for (int c = 0; c < 32; c++) {
            const float* xp = xb + (c << 14);
            float val = w00 * xp[a00] + w01 * xp[a01] + w10 * xp[a10] + w11 * xp[a11];
            ull v2 = pk2(val, val);
            const ulonglong2* wp = (const ulonglong2*)(wbuf + (k*32 + c)*32);
            #pragma unroll
            for (int i = 0; i < 8; i++) {
                ulonglong2 u = wp[i];
                fma2(acc2[2*i],   v2, u.x, acc2[2*i]);
                fma2(acc2[2*i+1], v2, u.y, acc2[2*i+1]);
            }
        }
    }
    float* x3p = g_x3 + ((long)b << 19) + y*128 + x0i;
    #pragma unroll
    for (int i = 0; i < 16; i++) {
        float a, bfl; upk2(a, bfl, acc2[i]);
        x3p[(2*i) << 14]   = a;
        x3p[(2*i+1) << 14] = bfl;
    }
}

// ---------------- kernel 4: switch-conv via tf32 tensor cores (R13, kept) ----------------
__global__ __launch_bounds__(256) void k_conv(
    const float* __restrict__ x,
    const float* __restrict__ sw_w1, const float* __restrict__ sw_b1,
    const float* __restrict__ sw_w2, const float* __restrict__ sw_b2,
    float* __restrict__ out)
{
    __shared__ __align__(16) float xs[64][136];
    __shared__ __align__(16) uint2 w1f[8][4][32];
    __shared__ float w2s[64], b1s[32], b2s[2];
    __shared__ float ysps[32], ychs[32];
    __shared__ float sbuf[2][128];

    int tid = threadIdx.x;
    int p0 = blockIdx.x * 128;
    int b = p0 >> 14, sp0 = p0 & 16383;
    long gbase = ((long)b << 19) + sp0;

    for (int i = tid; i < 8192; i += 256) {
        int c = i >> 7, px = i & 127;
        xs[c][px] = (c < 32) ? x[gbase + ((long)c << 14) + px]
                             : g_x3[gbase + ((long)(c - 32) << 14) + px];
    }
    for (int i = tid; i < 1024; i += 256) {
        int t = i >> 7, rem2 = i & 127, n = rem2 >> 5, lane = rem2 & 31;
        int k = t*8 + (lane & 3), o = n*8 + (lane >> 2);
        w1f[t][n][lane] = make_uint2(tf32c(sw_w1[o*64 + k]), tf32c(sw_w1[o*64 + k + 4]));
    }
    if (tid < 64) w2s[tid] = sw_w2[tid];
    if (tid < 32) { b1s[tid] = sw_b1[tid]; ysps[tid] = g_ysp[b*32 + tid]; ychs[tid] = g_ych[b*32 + tid]; }
    if (tid < 2)  b2s[tid] = sw_b2[tid];
    __syncthreads();

    int w = tid >> 5, lane = tid & 31;
    int r = lane >> 2, q = lane & 3;
    int m0 = w * 16;

    float d[4][4] = {{0.f}};
    #pragma unroll
    for (int t = 0; t < 8; t++) {
        uint32_t a0 = tf32c(xs[t*8 + q    ][m0 + r]);
        uint32_t a1 = tf32c(xs[t*8 + q    ][m0 + r + 8]);
        uint32_t a2 = tf32c(xs[t*8 + q + 4][m0 + r]);
        uint32_t a3 = tf32c(xs[t*8 + q + 4][m0 + r + 8]);
        #pragma unroll
        for (int n = 0; n < 4; n++) {
            uint2 bf = w1f[t][n][lane];
            MMA168(d[n][0], d[n][1], d[n][2], d[n][3], a0, a1, a2, a3, bf.x, bf.y);
        }
    }
    float sA0 = 0.f, sA1 = 0.f, sB0 = 0.f, sB1 = 0.f;
    #pragma unroll
    for (int n = 0; n < 4; n++) {
        int o0 = n*8 + 2*q, o1 = o0 + 1;
        float h00 = fmaxf(d[n][0] + b1s[o0], 0.f);
        float h01 = fmaxf(d[n][1] + b1s[o1], 0.f);
        float h10 = fmaxf(d[n][2] + b1s[o0], 0.f);
        float h11 = fmaxf(d[n][3] + b1s[o1], 0.f);
        sA0 += h00*w2s[o0]      + h01*w2s[o1];
        sA1 += h00*w2s[32 + o0] + h01*w2s[32 + o1];
        sB0 += h10*w2s[o0]      + h11*w2s[o1];
        sB1 += h10*w2s[32 + o0] + h11*w2s[32 + o1];
    }
    sA0 += __shfl_xor_sync(0xffffffffu, sA0, 1); sA0 += __shfl_xor_sync(0xffffffffu, sA0, 2);
    sA1 += __shfl_xor_sync(0xffffffffu, sA1, 1); sA1 += __shfl_xor_sync(0xffffffffu, sA1, 2);
    sB0 += __shfl_xor_sync(0xffffffffu, sB0, 1); sB0 += __shfl_xor_sync(0xffffffffu, sB0, 2);
    sB1 += __shfl_xor_sync(0xffffffffu, sB1, 1); sB1 += __shfl_xor_sync(0xffffffffu, sB1, 2);
    if (q == 0) {
        sbuf[0][m0 + r]     = 1.f / (1.f + __expf(-(sA0 + b2s[0])));
        sbuf[1][m0 + r]     = 1.f / (1.f + __expf(-(sA1 + b2s[1])));
        sbuf[0][m0 + r + 8] = 1.f / (1.f + __expf(-(sB0 + b2s[0])));
        sbuf[1][m0 + r + 8] = 1.f / (1.f + __expf(-(sB1 + b2s[1])));
    }
    __syncthreads();
    for (int i = tid; i < 4096; i += 256) {
        int c = i >> 7, px = i & 127;
        out[gbase + ((long)c << 14) + px] = xs[c][px] + ysps[c]*sbuf[0][px] + ychs[c]*sbuf[1][px];
    }
}

// ---------------- kernel 5: memory attention via tf32 tensor cores (R12) ----------------
__global__ __launch_bounds__(256) void k_attn(
    const float* __restrict__ mem, float* __restrict__ out)
{
    __shared__ __align__(16) uint2 b1buf[64*32];
    __shared__ __align__(16) uint2 b2buf[64*32];
    int tid = threadIdx.x;
    int hd = blockIdx.y;
    const float RSL = 0.35355339059327373f * 1.4426950408889634f;
    const int SIG[8] = {0,4,1,5,2,6,3,7};

    const float* mh = mem + hd*MSIZE*HD;
    for (int j = tid; j < 2048; j += 256) {
        int t = j >> 5, i = j & 31;
        int c = i >> 2, r = i & 3;
        int s1 = 8*t + SIG[c];
        b1buf[j] = make_uint2(tf32c(mh[s1*8 + r] * RSL), tf32c(mh[s1*8 + r + 4] * RSL));
        b2buf[j] = make_uint2(tf32c(mh[(8*t + r)*8 + c]), tf32c(mh[(8*t + r + 4)*8 + c]));
    }
    __syncthreads();

    int w = tid >> 5, lane = tid & 31;
    int p0 = blockIdx.x * 128 + w * 16;
    int b = p0 >> 14, sp0 = p0 & 16383;
    int r = lane >> 2, q = lane & 3;
    long base = ((long)b << 19) + ((long)(hd*8) << 14);
    int spA = sp0 + r, spB = sp0 + r + 8;

    uint32_t a0 = tf32c(out[base + ((long)q << 14) + spA]);
    uint32_t a1 = tf32c(out[base + ((long)q << 14) + spB]);
    uint32_t a2 = tf32c(out[base + ((long)(q+4) << 14) + spA]);
    uint32_t a3 = tf32c(out[base + ((long)(q+4) << 14) + spB]);

    float cE0=0.f,cE1=0.f,cE2=0.f,cE3=0.f;
    float cO0=0.f,cO1=0.f,cO2=0.f,cO3=0.f;
    float ls0 = 0.f, ls1 = 0.f;

    #pragma unroll 4
    for (int t = 0; t < 64; t += 2) {
        {
            uint2 b1 = b1buf[t*32 + lane];
            float s0=0.f,s1v=0.f,s2=0.f,s3=0.f;
            MMA168(s0,s1v,s2,s3, a0,a1,a2,a3, b1.x,b1.y);
            float e0 = ex2f(s0), e1 = ex2f(s1v), e2 = ex2f(s2), e3 = ex2f(s3);
            ls0 += e0 + e1; ls1 += e2 + e3;
            uint32_t pa0 = tf32c(e0), pa1 = tf32c(e2), pa2 = tf32c(e1), pa3 = tf32c(e3);
            uint2 b2 = b2buf[t*32 + lane];
            MMA168(cE0,cE1,cE2,cE3, pa0,pa1,pa2,pa3, b2.x,b2.y);
        }
        {
            uint2 b1 = b1buf[(t+1)*32 + lane];
            float s0=0.f,s1v=0.f,s2=0.f,s3=0.f;
            MMA168(s0,s1v,s2,s3, a0,a1,a2,a3, b1.x,b1.y);
            float e0 = ex2f(s0), e1 = ex2f(s1v), e2 = ex2f(s2), e3 = ex2f(s3);
            ls0 += e0 + e1; ls1 += e2 + e3;
            uint32_t pa0 = tf32c(e0), pa1 = tf32c(e2), pa2 = tf32c(e1), pa3 = tf32c(e3);
            uint2 b2 = b2buf[(t+1)*32 + lane];
            MMA168(cO0,cO1,cO2,cO3, pa0,pa1,pa2,pa3, b2.x,b2.y);
        }
    }
    float c0 = cE0 + cO0, c1 = cE1 + cO1, c2 = cE2 + cO2, c3 = cE3 + cO3;

    ls0 += __shfl_xor_sync(0xffffffffu, ls0, 1);
    ls0 += __shfl_xor_sync(0xffffffffu, ls0, 2);
    ls1 += __shfl_xor_sync(0xffffffffu, ls1, 1);
    ls1 += __shfl_xor_sync(0xffffffffu, ls1, 2);
    float inv0 = 1.f / ls0, inv1 = 1.f / ls1;

    long oA0 = base + ((long)(2*q)   << 14) + spA;
    long oA1 = base + ((long)(2*q+1) << 14) + spA;
    long oB0 = base + ((long)(2*q)   << 14) + spB;
    long oB1 = base + ((long)(2*q+1) << 14) + spB;
    out[oA0] += c0 * inv0;
    out[oA1] += c1 * inv0;
    out[oB0] += c2 * inv1;
    out[oB1] += c3 * inv1;
}

extern "C" void kernel_launch(void* const* d_in, const int* in_sizes, int n_in,
                              void* d_out, int out_size) {
    const float* x     = (const float*)d_in[0];
    const float* fs_w1 = (const float*)d_in[1];
    const float* fs_w2 = (const float*)d_in[2];
    const float* fc_w1 = (const float*)d_in[3];
    const float* fc_w2 = (const float*)d_in[4];
    const float* sw_w1 = (const float*)d_in[5];
    const float* sw_b1 = (const float*)d_in[6];
    const float* sw_w2 = (const float*)d_in[7];
    const float* sw_b2 = (const float*)d_in[8];
    const float* off_w = (const float*)d_in[9];
    const float* off_b = (const float*)d_in[10];
    const float* dcn_w = (const float*)d_in[11];
    const float* dcn_b = (const float*)d_in[12];
    const float* mem   = (const float*)d_in[13];
    float* out = (float*)d_out;

    k_avg<<<Bq*Cc, 256>>>(x);
    k_mlp<<<1, 128>>>(fs_w1, fs_w2, fc_w1, fc_w2);
    k_off<<<256, 128>>>(x, off_w, off_b);
    k_dcn2<<<BHW/256, 256>>>(x, dcn_w, dcn_b);
    k_conv<<<BHW/128, 256>>>(x, sw_w1, sw_b1, sw_w2, sw_b2, out);
    dim3 ag(BHW/128, 4);
    k_attn<<<ag, 256>>>(mem, out);
}

// round 15
// speedup vs baseline: 1.2236x; 1.1794x over previous
#include <cuda_runtime.h>
#include <math.h>
#include <stdint.h>

#define Bq 4
#define Cc 32
#define Hh 128
#define Ww 128
#define HW (Hh*Ww)
#define BHW (Bq*HW)
#define MSIZE 512
#define HD 8

typedef unsigned long long ull;

__device__ __forceinline__ ull pk2(float lo, float hi) {
    ull r; asm("mov.b64 %0,{%1,%2};" : "=l"(r) : "f"(lo), "f"(hi)); return r;
}
__device__ __forceinline__ void upk2(float& lo, float& hi, ull v) {
    asm("mov.b64 {%0,%1},%2;" : "=f"(lo), "=f"(hi) : "l"(v));
}
__device__ __forceinline__ void fma2(ull& d, ull a, ull b, ull c) {
    asm("fma.rn.f32x2 %0,%1,%2,%3;" : "=l"(d) : "l"(a), "l"(b), "l"(c));
}
__device__ __forceinline__ float ex2f(float x) {
    float r; asm("ex2.approx.f32 %0,%1;" : "=f"(r) : "f"(x)); return r;
}
__device__ __forceinline__ uint32_t tf32c(float f) {
    uint32_t r; asm("cvt.rna.tf32.f32 %0,%1;" : "=r"(r) : "f"(f)); return r;
}
__device__ __forceinline__ uint32_t bfx2(float lo, float hi) {
    uint32_t r; asm("cvt.rn.bf16x2.f32 %0,%1,%2;" : "=r"(r) : "f"(hi), "f"(lo)); return r;
}
#define MMA168(d0,d1,d2,d3,a0,a1,a2,a3,b0,b1) \
  asm("mma.sync.aligned.m16n8k8.row.col.f32.tf32.tf32.f32 " \
      "{%0,%1,%2,%3}, {%4,%5,%6,%7}, {%8,%9}, {%0,%1,%2,%3};" \
      : "+f"(d0),"+f"(d1),"+f"(d2),"+f"(d3) \
      : "r"(a0),"r"(a1),"r"(a2),"r"(a3),"r"(b0),"r"(b1))
#define MMAB16(d0,d1,d2,d3,a0,a1,a2,a3,b0,b1) \
  asm("mma.sync.aligned.m16n8k16.row.col.f32.bf16.bf16.f32 " \
      "{%0,%1,%2,%3}, {%4,%5,%6,%7}, {%8,%9}, {%0,%1,%2,%3};" \
      : "+f"(d0),"+f"(d1),"+f"(d2),"+f"(d3) \
      : "r"(a0),"r"(a1),"r"(a2),"r"(a3),"r"(b0),"r"(b1))

// scratch (no allocs allowed)
__device__ float g_x3[Bq*Cc*HW];
__device__ float g_om[27*BHW];     // offset-conv output, [j][p]
__device__ float g_yavg[Bq*Cc];
__device__ float g_ysp[Bq*Cc];
__device__ float g_ych[Bq*Cc];

// ---------------- kernel 1: per-(b,c) spatial mean ----------------
__global__ void k_avg(const float* __restrict__ x) {
    int bc = blockIdx.x;
    const float* p = x + bc * HW;
    float s = 0.f;
    for (int i = threadIdx.x; i < HW; i += 256) s += p[i];
    __shared__ float red[256];
    red[threadIdx.x] = s; __syncthreads();
    for (int st = 128; st > 0; st >>= 1) {
        if (threadIdx.x < st) red[threadIdx.x] += red[threadIdx.x + st];
        __syncthreads();
    }
    if (threadIdx.x == 0) g_yavg[bc] = red[0] * (1.0f / (float)HW);
}

// ---------------- kernel 2: tiny squeeze MLPs ----------------
__global__ void k_mlp(const float* __restrict__ fs_w1, const float* __restrict__ fs_w2,
                      const float* __restrict__ fc_w1, const float* __restrict__ fc_w2) {
    __shared__ float ys[Bq*Cc];
    int t = threadIdx.x;           // 128 threads, t = b*32+c
    ys[t] = g_yavg[t];
    __syncthreads();
    int b = t >> 5, c = t & 31;
    const float* yb = ys + b * 32;
    float hs0 = 0.f, hs1 = 0.f;
    #pragma unroll
    for (int j = 0; j < 32; j++) { hs0 += yb[j] * fs_w1[j]; hs1 += yb[j] * fs_w1[32 + j]; }
    hs0 = fmaxf(hs0, 0.f); hs1 = fmaxf(hs1, 0.f);
    float sp = hs0 * fs_w2[c*2 + 0] + hs1 * fs_w2[c*2 + 1];
    g_ysp[t] = 1.f / (1.f + __expf(-sp));
    float ch = 0.f;
    #pragma unroll
    for (int r = 0; r < 4; r++) {
        float a = 0.f;
        #pragma unroll
        for (int j = 0; j < 32; j++) a += yb[j] * fc_w1[r*32 + j];
        ch += fmaxf(a, 0.f) * fc_w2[c*4 + r];
    }
    g_ych[t] = 1.f / (1.f + __expf(-ch));
}

// ---------------- kernel 3a: offset conv (3x3, 32->27) ----------------
__global__ __launch_bounds__(128) void k_off(
    const float* __restrict__ x,
    const float* __restrict__ off_w, const float* __restrict__ off_b)
{
    __shared__ __align__(16) float wbuf[9*32*28];
    __shared__ float bbuf[28];
    int tid = threadIdx.x;
    for (int i = tid; i < 7776; i += 128) {
        int j = i / 288, r = i - j*288, c = r / 9, k = r - c*9;
        wbuf[(k*32 + c)*28 + j] = off_w[i];
    }
    for (int i = tid; i < 288; i += 128) wbuf[i*28 + 27] = 0.f;
    if (tid < 27) bbuf[tid] = off_b[tid];
    if (tid == 27) bbuf[27] = 0.f;
    __syncthreads();

    int x0i = tid;
    int b  = blockIdx.x >> 6;
    int y0 = (blockIdx.x & 63) * 2;
    const float* xb = x + ((long)b << 19);

    ull omA[14], omB[14];
    #pragma unroll
    for (int j = 0; j < 14; j++) { omA[j] = pk2(bbuf[2*j], bbuf[2*j+1]); omB[j] = omA[j]; }

    for (int ky = 0; ky < 3; ky++) {
        int yyA = y0 + ky - 1;
        int yyB = yyA + 1;
        bool okA = (yyA >= 0) & (yyA <= 127);
        bool okB = (yyB >= 0) & (yyB <= 127);
        for (int kx = 0; kx < 3; kx++) {
            int xx = x0i + kx - 1;
            bool okx = (xx >= 0) & (xx <= 127);
            bool vA = okA & okx, vB = okB & okx;
            if (!vA && !vB) continue;
            int kidx = ky*3 + kx;
            const float* xpA = xb + yyA*128 + xx;
            const float* xpB = xpA + 128;
            const float* wb0 = wbuf + kidx*32*28;
            #pragma unroll 4
            for (int c = 0; c < 32; c++) {
                float a = vA ? xpA[c << 14] : 0.f;
                float bb = vB ? xpB[c << 14] : 0.f;
                ull a2 = pk2(a, a), b2 = pk2(bb, bb);
                const ulonglong2* wp = (const ulonglong2*)(wb0 + c*28);
                #pragma unroll
                for (int i = 0; i < 7; i++) {
                    ulonglong2 u = wp[i];
                    fma2(omA[2*i],   a2, u.x, omA[2*i]);
                    fma2(omA[2*i+1], a2, u.y, omA[2*i+1]);
                    fma2(omB[2*i],   b2, u.x, omB[2*i]);
                    fma2(omB[2*i+1], b2, u.y, omB[2*i+1]);
                }
            }
        }
    }
    int pA = (b << 14) + y0*128 + x0i;
    int pB = pA + 128;
    #pragma unroll
    for (int j = 0; j < 14; j++) {
        float a0, a1; upk2(a0, a1, omA[j]);
        float b0, b1; upk2(b0, b1, omB[j]);
        g_om[(2*j)*BHW + pA] = a0;
        g_om[(2*j)*BHW + pB] = b0;
        if (2*j + 1 < 27) {
            g_om[(2*j+1)*BHW + pA] = a1;
            g_om[(2*j+1)*BHW + pB] = b1;
        }
    }
}

// ---------------- kernel 3b: deformable gather + 3x3 conv via bf16 mma ----------------
// Block = 128 px (one row), 256 threads. x3 only feeds sigmoid gates downstream,
// so bf16 accumulation error (~2e-3 on x3) is attenuated to ~1e-5 on the output.
// Per k-tap: (A) 128 thr bilinear params; (B) gather 2thr/px -> bf16x2 pairs;
// (C) per-warp m16n8k16 bf16 mma into persistent f32 D frags.
__global__ __launch_bounds__(256) void k_dcn2(
    const float* __restrict__ x,
    const float* __restrict__ dcn_w, const float* __restrict__ dcn_b)
{
    __shared__ __align__(16) uint32_t sampb[16][136];  // 8.7KB: bf16x2 (c even, c odd)
    __shared__ __align__(16) uint2 wf[2304];           // 18.4KB: B frags [k][kt][n][lane]
    __shared__ __align__(16) float4 pw4[128];
    __shared__ __align__(16) int4   pa4[128];
    __shared__ float bbuf[32];
    int tid = threadIdx.x;

    // B frags: W[k][c][o] = dcn_w[o*288 + c*9 + k]
    for (int i = tid; i < 2304; i += 256) {
        int k = i >> 8, rem = i & 255;
        int kt = rem >> 7, n = (rem >> 5) & 3, lane = i & 31;
        int q = lane & 3, r = lane >> 2;
        int row0 = 16*kt + 2*q, col = 8*n + r;
        float w00 = dcn_w[col*288 + row0*9 + k];
        float w01 = dcn_w[col*288 + (row0+1)*9 + k];
        float w80 = dcn_w[col*288 + (row0+8)*9 + k];
        float w81 = dcn_w[col*288 + (row0+9)*9 + k];
        wf[i] = make_uint2(bfx2(w00, w01), bfx2(w80, w81));
    }
    if (tid < 32) bbuf[tid] = dcn_b[tid];

    int px = tid & 127;
    int hi = tid >> 7;
    int b = blockIdx.x >> 7;
    int y = blockIdx.x & 127;
    int p0 = blockIdx.x * 128;
    int sp0 = p0 & 16383;
    const float* xb = x + ((long)b << 19);

    int w = tid >> 5, lane = tid & 31;
    int r = lane >> 2, q = lane & 3;
    int m0 = (w & 7) * 16;

    float d[4][4] = {{0.f}};

    for (int k = 0; k < 9; k++) {
        // ---- phase A: bilinear params ----
        if (tid < 128) {
            int p = (b << 14) + y*128 + tid;
            float ofy = g_om[(2*k)*BHW + p];
            float ofx = g_om[(2*k+1)*BHW + p];
            float msk = 1.f / (1.f + __expf(-g_om[(18+k)*BHW + p]));
            float py  = (float)(y + k/3 - 1) + ofy;
            float pxf = (float)(tid + k%3 - 1) + ofx;
            py  = fminf(fmaxf(py, -4.0f), 131.0f);
            pxf = fminf(fmaxf(pxf, -4.0f), 131.0f);
            float fy = floorf(py), fx = floorf(pxf);
            float wy = py - fy, wx = pxf - fx;
            int iy0 = (int)fy, ix0 = (int)fx, iy1 = iy0+1, ix1 = ix0+1;
            float vy0 = (iy0 >= 0 && iy0 <= 127) ? 1.f : 0.f;
            float vy1 = (iy1 >= 0 && iy1 <= 127) ? 1.f : 0.f;
            float vx0 = (ix0 >= 0 && ix0 <= 127) ? 1.f : 0.f;
            float vx1 = (ix1 >= 0 && ix1 <= 127) ? 1.f : 0.f;
            pw4[tid] = make_float4((1.f-wy)*(1.f-wx)*vy0*vx0*msk,
                                   (1.f-wy)*wx      *vy0*vx1*msk,
                                   wy      *(1.f-wx)*vy1*vx0*msk,
                                   wy      *wx      *vy1*vx1*msk);
            int cy0 = min(max(iy0,0),127), cy1 = min(max(iy1,0),127);
            int cx0 = min(max(ix0,0),127), cx1 = min(max(ix1,0),127);
            pa4[tid] = make_int4(cy0*128+cx0, cy0*128+cx1, cy1*128+cx0, cy1*128+cx1);
        }
        __syncthreads();
        // ---- phase B: gather, pack bf16x2 channel pairs ----
        {
            float4 wv = pw4[px];
            int4   av = pa4[px];
            #pragma unroll 4
            for (int cp = 0; cp < 8; cp++) {
                int c0 = (hi*8 + cp)*2;
                const float* xp0 = xb + ((long)c0 << 14);
                const float* xp1 = xp0 + (1 << 14);
                float v0 = wv.x*xp0[av.x] + wv.y*xp0[av.y] + wv.z*xp0[av.z] + wv.w*xp0[av.w];
                float v1 = wv.x*xp1[av.x] + wv.y*xp1[av.y] + wv.z*xp1[av.z] + wv.w*xp1[av.w];
                sampb[hi*8 + cp][px] = bfx2(v0, v1);
            }
        }
        __syncthreads();
        // ---- phase C: bf16 mma ----
        #pragma unroll
        for (int kt = 0; kt < 2; kt++) {
            uint32_t a0 = sampb[8*kt + q    ][m0 + r];
            uint32_t a1 = sampb[8*kt + q    ][m0 + r + 8];
            uint32_t a2 = sampb[8*kt + q + 4][m0 + r];
            uint32_t a3 = sampb[8*kt + q + 4][m0 + r + 8];
            #pragma unroll
            for (int n = 0; n < 4; n++) {
                uint2 bf = wf[((k*2 + kt)*4 + n)*32 + lane];
                MMAB16(d[n][0], d[n][1], d[n][2], d[n][3], a0, a1, a2, a3, bf.x, bf.y);
            }
        }
        __syncthreads();
    }
    long gb = ((long)b << 19) + sp0;
    #pragma unroll
    for (int n = 0; n < 4; n++) {
        int o0 = 8*n + 2*q, o1 = o0 + 1;
        g_x3[gb + ((long)o0 << 14) + m0 + r]     = d[n][0] + bbuf[o0];
        g_x3[gb + ((long)o1 << 14) + m0 + r]     = d[n][1] + bbuf[o1];
        g_x3[gb + ((long)o0 << 14) + m0 + r + 8] = d[n][2] + bbuf[o0];
        g_x3[gb + ((long)o1 << 14) + m0 + r + 8] = d[n][3] + bbuf[o1];
    }
}

// ---------------- kernel 4: switch-conv via tf32 tensor cores ----------------
__global__ __launch_bounds__(256) void k_conv(
    const float* __restrict__ x,
    const float* __restrict__ sw_w1, const float* __restrict__ sw_b1,
    const float* __restrict__ sw_w2, const float* __restrict__ sw_b2,
    float* __restrict__ out)
{
    __shared__ __align__(16) float xs[64][136];
    __shared__ __align__(16) uint2 w1f[8][4][32];
    __shared__ float w2s[64], b1s[32], b2s[2];
    __shared__ float ysps[32], ychs[32];
    __shared__ float sbuf[2][128];

    int tid = threadIdx.x;
    int p0 = blockIdx.x * 128;
    int b = p0 >> 14, sp0 = p0 & 16383;
    long gbase = ((long)b << 19) + sp0;

    for (int i = tid; i < 8192; i += 256) {
        int c = i >> 7, px = i & 127;
        xs[c][px] = (c < 32) ? x[gbase + ((long)c << 14) + px]
                             : g_x3[gbase + ((long)(c - 32) << 14) + px];
    }
    for (int i = tid; i < 1024; i += 256) {
        int t = i >> 7, rem2 = i & 127, n = rem2 >> 5, lane = rem2 & 31;
        int k = t*8 + (lane & 3), o = n*8 + (lane >> 2);
        w1f[t][n][lane] = make_uint2(tf32c(sw_w1[o*64 + k]), tf32c(sw_w1[o*64 + k + 4]));
    }
    if (tid < 64) w2s[tid] = sw_w2[tid];
    if (tid < 32) { b1s[tid] = sw_b1[tid]; ysps[tid] = g_ysp[b*32 + tid]; ychs[tid] = g_ych[b*32 + tid]; }
    if (tid < 2)  b2s[tid] = sw_b2[tid];
    __syncthreads();

    int w = tid >> 5, lane = tid & 31;
    int r = lane >> 2, q = lane & 3;
    int m0 = w * 16;

    float d[4][4] = {{0.f}};
    #pragma unroll
    for (int t = 0; t < 8; t++) {
        uint32_t a0 = tf32c(xs[t*8 + q    ][m0 + r]);
        uint32_t a1 = tf32c(xs[t*8 + q    ][m0 + r + 8]);
        uint32_t a2 = tf32c(xs[t*8 + q + 4][m0 + r]);
        uint32_t a3 = tf32c(xs[t*8 + q + 4][m0 + r + 8]);
        #pragma unroll
        for (int n = 0; n < 4; n++) {
            uint2 bf = w1f[t][n][lane];
            MMA168(d[n][0], d[n][1], d[n][2], d[n][3], a0, a1, a2, a3, bf.x, bf.y);
        }
    }
    float sA0 = 0.f, sA1 = 0.f, sB0 = 0.f, sB1 = 0.f;
    #pragma unroll
    for (int n = 0; n < 4; n++) {
        int o0 = n*8 + 2*q, o1 = o0 + 1;
        float h00 = fmaxf(d[n][0] + b1s[o0], 0.f);
        float h01 = fmaxf(d[n][1] + b1s[o1], 0.f);
        float h10 = fmaxf(d[n][2] + b1s[o0], 0.f);
        float h11 = fmaxf(d[n][3] + b1s[o1], 0.f);
        sA0 += h00*w2s[o0]      + h01*w2s[o1];
        sA1 += h00*w2s[32 + o0] + h01*w2s[32 + o1];
        sB0 += h10*w2s[o0]      + h11*w2s[o1];
        sB1 += h10*w2s[32 + o0] + h11*w2s[32 + o1];
    }
    sA0 += __shfl_xor_sync(0xffffffffu, sA0, 1); sA0 += __shfl_xor_sync(0xffffffffu, sA0, 2);
    sA1 += __shfl_xor_sync(0xffffffffu, sA1, 1); sA1 += __shfl_xor_sync(0xffffffffu, sA1, 2);
    sB0 += __shfl_xor_sync(0xffffffffu, sB0, 1); sB0 += __shfl_xor_sync(0xffffffffu, sB0, 2);
    sB1 += __shfl_xor_sync(0xffffffffu, sB1, 1); sB1 += __shfl_xor_sync(0xffffffffu, sB1, 2);
    if (q == 0) {
        sbuf[0][m0 + r]     = 1.f / (1.f + __expf(-(sA0 + b2s[0])));
        sbuf[1][m0 + r]     = 1.f / (1.f + __expf(-(sA1 + b2s[1])));
        sbuf[0][m0 + r + 8] = 1.f / (1.f + __expf(-(sB0 + b2s[0])));
        sbuf[1][m0 + r + 8] = 1.f / (1.f + __expf(-(sB1 + b2s[1])));
    }
    __syncthreads();
    for (int i = tid; i < 4096; i += 256) {
        int c = i >> 7, px = i & 127;
        out[gbase + ((long)c << 14) + px] = xs[c][px] + ysps[c]*sbuf[0][px] + ychs[c]*sbuf[1][px];
    }
}

// ---------------- kernel 5: memory attention via tf32 tensor cores ----------------
__global__ __launch_bounds__(256) void k_attn(
    const float* __restrict__ mem, float* __restrict__ out)
{
    __shared__ __align__(16) uint2 b1buf[64*32];
    __shared__ __align__(16) uint2 b2buf[64*32];
    int tid = threadIdx.x;
    int hd = blockIdx.y;
    const float RSL = 0.35355339059327373f * 1.4426950408889634f;
    const int SIG[8] = {0,4,1,5,2,6,3,7};

    const float* mh = mem + hd*MSIZE*HD;
    for (int j = tid; j < 2048; j += 256) {
        int t = j >> 5, i = j & 31;
        int c = i >> 2, r = i & 3;
        int s1 = 8*t + SIG[c];
        b1buf[j] = make_uint2(tf32c(mh[s1*8 + r] * RSL), tf32c(mh[s1*8 + r + 4] * RSL));
        b2buf[j] = make_uint2(tf32c(mh[(8*t + r)*8 + c]), tf32c(mh[(8*t + r + 4)*8 + c]));
    }
    __syncthreads();

    int w = tid >> 5, lane = tid & 31;
    int p0 = blockIdx.x * 128 + w * 16;
    int b = p0 >> 14, sp0 = p0 & 16383;
    int r = lane >> 2, q = lane & 3;
    long base = ((long)b << 19) + ((long)(hd*8) << 14);
    int spA = sp0 + r, spB = sp0 + r + 8;

    uint32_t a0 = tf32c(out[base + ((long)q << 14) + spA]);
    uint32_t a1 = tf32c(out[base + ((long)q << 14) + spB]);
    uint32_t a2 = tf32c(out[base + ((long)(q+4) << 14) + spA]);
    uint32_t a3 = tf32c(out[base + ((long)(q+4) << 14) + spB]);

    float cE0=0.f,cE1=0.f,cE2=0.f,cE3=0.f;
    float cO0=0.f,cO1=0.f,cO2=0.f,cO3=0.f;
    float ls0 = 0.f, ls1 = 0.f;

    #pragma unroll 4
    for (int t = 0; t < 64; t += 2) {
        {
            uint2 b1 = b1buf[t*32 + lane];
            float s0=0.f,s1v=0.f,s2=0.f,s3=0.f;
            MMA168(s0,s1v,s2,s3, a0,a1,a2,a3, b1.x,b1.y);
            float e0 = ex2f(s0), e1 = ex2f(s1v), e2 = ex2f(s2), e3 = ex2f(s3);
            ls0 += e0 + e1; ls1 += e2 + e3;
            uint32_t pa0 = tf32c(e0), pa1 = tf32c(e2), pa2 = tf32c(e1), pa3 = tf32c(e3);
            uint2 b2 = b2buf[t*32 + lane];
            MMA168(cE0,cE1,cE2,cE3, pa0,pa1,pa2,pa3, b2.x,b2.y);
        }
        {
            uint2 b1 = b1buf[(t+1)*32 + lane];
            float s0=0.f,s1v=0.f,s2=0.f,s3=0.f;
            MMA168(s0,s1v,s2,s3, a0,a1,a2,a3, b1.x,b1.y);
            float e0 = ex2f(s0), e1 = ex2f(s1v), e2 = ex2f(s2), e3 = ex2f(s3);
            ls0 += e0 + e1; ls1 += e2 + e3;
            uint32_t pa0 = tf32c(e0), pa1 = tf32c(e2), pa2 = tf32c(e1), pa3 = tf32c(e3);
            uint2 b2 = b2buf[(t+1)*32 + lane];
            MMA168(cO0,cO1,cO2,cO3, pa0,pa1,pa2,pa3, b2.x,b2.y);
        }
    }
    float c0 = cE0 + cO0, c1 = cE1 + cO1, c2 = cE2 + cO2, c3 = cE3 + cO3;

    ls0 += __shfl_xor_sync(0xffffffffu, ls0, 1);
    ls0 += __shfl_xor_sync(0xffffffffu, ls0, 2);
    ls1 += __shfl_xor_sync(0xffffffffu, ls1, 1);
    ls1 += __shfl_xor_sync(0xffffffffu, ls1, 2);
    float inv0 = 1.f / ls0, inv1 = 1.f / ls1;

    long oA0 = base + ((long)(2*q)   << 14) + spA;
    long oA1 = base + ((long)(2*q+1) << 14) + spA;
    long oB0 = base + ((long)(2*q)   << 14) + spB;
    long oB1 = base + ((long)(2*q+1) << 14) + spB;
    out[oA0] += c0 * inv0;
    out[oA1] += c1 * inv0;
    out[oB0] += c2 * inv1;
    out[oB1] += c3 * inv1;
}

extern "C" void kernel_launch(void* const* d_in, const int* in_sizes, int n_in,
                              void* d_out, int out_size) {
    const float* x     = (const float*)d_in[0];
    const float* fs_w1 = (const float*)d_in[1];
    const float* fs_w2 = (const float*)d_in[2];
    const float* fc_w1 = (const float*)d_in[3];
    const float* fc_w2 = (const float*)d_in[4];
    const float* sw_w1 = (const float*)d_in[5];
    const float* sw_b1 = (const float*)d_in[6];
    const float* sw_w2 = (const float*)d_in[7];
    const float* sw_b2 = (const float*)d_in[8];
    const float* off_w = (const float*)d_in[9];
    const float* off_b = (const float*)d_in[10];
    const float* dcn_w = (const float*)d_in[11];
    const float* dcn_b = (const float*)d_in[12];
    const float* mem   = (const float*)d_in[13];
    float* out = (float*)d_out;

    k_avg<<<Bq*Cc, 256>>>(x);
    k_mlp<<<1, 128>>>(fs_w1, fs_w2, fc_w1, fc_w2);
    k_off<<<256, 128>>>(x, off_w, off_b);
    k_dcn2<<<BHW/128, 256>>>(x, dcn_w, dcn_b);
    k_conv<<<BHW/128, 256>>>(x, sw_w1, sw_b1, sw_w2, sw_b2, out);
    dim3 ag(BHW/128, 4);
    k_attn<<<ag, 256>>>(mem, out);
}